// round 1
// baseline (speedup 1.0000x reference)
#include <cuda_runtime.h>
#include <math.h>

#define DIMV 2048
#define NTR  4096
#define MDEVR 8192
#define TST  500
#define ETA  0.1f
#define NTHREADS 256
#define NWARPS 8
#define MAXCTA 160

// Persistent device state (static allocation — no cudaMalloc anywhere)
__device__ float    g_theta[DIMV];
__device__ float    g_devpart[MAXCTA];
__device__ float    g_gradpart[MAXCTA * DIMV];
__device__ unsigned g_arrive;

// ---------------------------------------------------------------------------
__global__ void ak_init(const float* __restrict__ theta0,
                        float* __restrict__ out, int out_size) {
    int i = blockIdx.x * blockDim.x + threadIdx.x;
    if (i == 0) g_arrive = 0u;
    if (i < DIMV) g_theta[i] = theta0[i];
    // zero any tail of the output buffer beyond [loss, full_losses]
    for (int j = TST + 1 + i; j < out_size; j += gridDim.x * blockDim.x)
        out[j] = 0.0f;
}

// Grid-wide barrier: atomic counter + generation, with gpu-scope fences
// (__threadfence -> CCTL.IVALL gives cross-SM visibility incl. L1 invalidate).
__device__ __forceinline__ void grid_barrier(unsigned nb) {
    __syncthreads();
    if (threadIdx.x == 0) {
        __threadfence();
        unsigned old = atomicAdd(&g_arrive, 1u);
        unsigned target = (old / nb + 1u) * nb;
        while (*((volatile unsigned*)&g_arrive) < target) { }
        __threadfence();
    }
    __syncthreads();
}

__device__ __forceinline__ float warp_sum(float v) {
#pragma unroll
    for (int o = 16; o; o >>= 1) v += __shfl_xor_sync(0xffffffffu, v, o);
    return v;
}

// stable softplus-based loss; matches reference's inf-patched log1p(exp(z))
__device__ __forceinline__ float dev_loss_elem(float z, float y) {
    return fmaxf(z, 0.0f) - y * z + log1pf(expf(-fabsf(z)));
}

// ---------------------------------------------------------------------------
__global__ void __launch_bounds__(NTHREADS, 1)
ak_train(const float* __restrict__ xn,  const float* __restrict__ yn,
         const float* __restrict__ dxn, const float* __restrict__ dyn,
         const float* __restrict__ alphas,
         float* __restrict__ out, int out_size) {
    extern __shared__ float sm[];
    float* s_grad = sm;                 // NWARPS * DIMV
    float* s_dev  = sm + NWARPS * DIMV; // NWARPS

    const int tid  = threadIdx.x;
    const int lane = tid & 31;
    const int w    = tid >> 5;
    const int cta  = blockIdx.x;
    const int ncta = gridDim.x;
    const int gw   = cta * NWARPS + w;
    const int nw   = ncta * NWARPS;

    float th[64];

    for (int t = 0; t < TST; ++t) {
        // ---- load theta into registers (lane owns elems (k*32+lane)*4 .. +3)
        {
            const float4* t4 = (const float4*)g_theta;
#pragma unroll
            for (int k = 0; k < 16; k++) {
                float4 v = t4[k * 32 + lane];
                th[4*k+0] = v.x; th[4*k+1] = v.y; th[4*k+2] = v.z; th[4*k+3] = v.w;
            }
        }

        // ---- train rows: dot + fused gradient accumulation (row reused from L1)
        float gacc[64];
#pragma unroll
        for (int j = 0; j < 64; j++) gacc[j] = 0.0f;

        for (int n = gw; n < NTR; n += nw) {
            const float4* xr = (const float4*)(xn + (size_t)n * DIMV);
            float acc = 0.0f;
#pragma unroll
            for (int k = 0; k < 16; k++) {
                float4 v = xr[k * 32 + lane];
                acc = fmaf(v.x, th[4*k+0], acc);
                acc = fmaf(v.y, th[4*k+1], acc);
                acc = fmaf(v.z, th[4*k+2], acc);
                acc = fmaf(v.w, th[4*k+3], acc);
            }
            float z  = warp_sum(acc);
            float sg = 1.0f / (1.0f + expf(-z));
            float coef = alphas[(size_t)t * NTR + n] * (sg - yn[n]);
#pragma unroll
            for (int k = 0; k < 16; k++) {
                float4 v = xr[k * 32 + lane];   // L1 hit (just loaded)
                gacc[4*k+0] = fmaf(coef, v.x, gacc[4*k+0]);
                gacc[4*k+1] = fmaf(coef, v.y, gacc[4*k+1]);
                gacc[4*k+2] = fmaf(coef, v.z, gacc[4*k+2]);
                gacc[4*k+3] = fmaf(coef, v.w, gacc[4*k+3]);
            }
        }
        // dump per-warp grad partial to smem (frees gacc regs for dev loop)
        {
            float4* gp = (float4*)(s_grad + w * DIMV);
#pragma unroll
            for (int k = 0; k < 16; k++) {
                float4 v;
                v.x = gacc[4*k+0]; v.y = gacc[4*k+1];
                v.z = gacc[4*k+2]; v.w = gacc[4*k+3];
                gp[k * 32 + lane] = v;
            }
        }

        // ---- dev loss partial with current theta (= full_losses[t])
        float dsum = 0.0f;
        for (int m = gw; m < MDEVR; m += nw) {
            const float4* xr = (const float4*)(dxn + (size_t)m * DIMV);
            float acc = 0.0f;
#pragma unroll
            for (int k = 0; k < 16; k++) {
                float4 v = xr[k * 32 + lane];
                acc = fmaf(v.x, th[4*k+0], acc);
                acc = fmaf(v.y, th[4*k+1], acc);
                acc = fmaf(v.z, th[4*k+2], acc);
                acc = fmaf(v.w, th[4*k+3], acc);
            }
            float z = warp_sum(acc);
            dsum += dev_loss_elem(z, dyn[m]);
        }
        if (lane == 0) s_dev[w] = dsum;
        __syncthreads();
        if (tid == 0) {
            float s = 0.0f;
#pragma unroll
            for (int i = 0; i < NWARPS; i++) s += s_dev[i];
            g_devpart[cta] = s;
        }
        // CTA-level grad partial (fixed order over warps -> deterministic)
#pragma unroll
        for (int i = 0; i < DIMV / NTHREADS; i++) {
            int d = tid + i * NTHREADS;
            float s = 0.0f;
#pragma unroll
            for (int ww = 0; ww < NWARPS; ww++) s += s_grad[ww * DIMV + d];
            g_gradpart[cta * DIMV + d] = s;
        }

        grid_barrier((unsigned)ncta);

        // ---- phase B: reduce partials, update theta, record loss
        {
            int gid = cta * NTHREADS + tid;
            if (ncta >= 128) {
                int d = gid >> 4, sub = gid & 15;
                if (d < DIMV) {
                    float s = 0.0f;
                    for (int r = sub; r < ncta; r += 16)
                        s += g_gradpart[r * DIMV + d];
#pragma unroll
                    for (int o = 8; o; o >>= 1)
                        s += __shfl_xor_sync(0xffffffffu, s, o);
                    if (sub == 0) g_theta[d] = g_theta[d] - ETA * s;
                }
            } else {
                for (int d = gid; d < DIMV; d += ncta * NTHREADS) {
                    float s = 0.0f;
                    for (int r = 0; r < ncta; r++) s += g_gradpart[r * DIMV + d];
                    g_theta[d] = g_theta[d] - ETA * s;
                }
            }
            if (cta == ncta - 1 && tid == 0) {
                float s = 0.0f;
                for (int c = 0; c < ncta; c++) s += g_devpart[c];
                float Lt = s * (1.0f / MDEVR);
                if (1 + t < out_size) out[1 + t] = Lt;   // full_losses[t]
            }
        }
        grid_barrier((unsigned)ncta);
    }

    // ---- final dev eval at theta_T (= i_losses[T-1]); finalize scalar loss
    {
        const float4* t4 = (const float4*)g_theta;
#pragma unroll
        for (int k = 0; k < 16; k++) {
            float4 v = t4[k * 32 + lane];
            th[4*k+0] = v.x; th[4*k+1] = v.y; th[4*k+2] = v.z; th[4*k+3] = v.w;
        }
        float dsum = 0.0f;
        for (int m = gw; m < MDEVR; m += nw) {
            const float4* xr = (const float4*)(dxn + (size_t)m * DIMV);
            float acc = 0.0f;
#pragma unroll
            for (int k = 0; k < 16; k++) {
                float4 v = xr[k * 32 + lane];
                acc = fmaf(v.x, th[4*k+0], acc);
                acc = fmaf(v.y, th[4*k+1], acc);
                acc = fmaf(v.z, th[4*k+2], acc);
                acc = fmaf(v.w, th[4*k+3], acc);
            }
            float z = warp_sum(acc);
            dsum += dev_loss_elem(z, dyn[m]);
        }
        if (lane == 0) s_dev[w] = dsum;
        __syncthreads();
        if (tid == 0) {
            float s = 0.0f;
#pragma unroll
            for (int i = 0; i < NWARPS; i++) s += s_dev[i];
            g_devpart[cta] = s;
        }
        grid_barrier((unsigned)ncta);
        if (cta == 0 && tid == 0) {
            float s = 0.0f;
            for (int c = 0; c < ncta; c++) s += g_devpart[c];
            float LT = s * (1.0f / MDEVR);
            // loss = (sum_{t=1}^{T-1} L_t + L_T) / T   (i_losses[t] == L_{t+1})
            float isum = 0.0f;
            for (int t = 1; t < TST; t++)
                isum += (1 + t < out_size) ? out[1 + t] : 0.0f;
            isum += LT;
            if (out_size > 0) out[0] = isum / (float)TST;
        }
    }
}

// ---------------------------------------------------------------------------
extern "C" void kernel_launch(void* const* d_in, const int* in_sizes, int n_in,
                              void* d_out, int out_size) {
    const float *theta = nullptr, *alphas = nullptr, *xn = nullptr,
                *yn = nullptr, *dxn = nullptr, *dyn = nullptr;
    for (int i = 0; i < n_in; i++) {
        switch (in_sizes[i]) {
            case DIMV:        theta  = (const float*)d_in[i]; break; // 2048
            case TST * NTR:   alphas = (const float*)d_in[i]; break; // 2048000
            case NTR * DIMV:  xn     = (const float*)d_in[i]; break; // 8388608
            case NTR:         yn     = (const float*)d_in[i]; break; // 4096
            case MDEVR * DIMV: dxn   = (const float*)d_in[i]; break; // 16777216
            case MDEVR:       dyn    = (const float*)d_in[i]; break; // 8192
            default: break;
        }
    }
    float* out = (float*)d_out;

    int dev = 0;
    cudaGetDevice(&dev);
    int nsm = 148;
    cudaDeviceGetAttribute(&nsm, cudaDevAttrMultiProcessorCount, dev);
    int ncta = nsm < MAXCTA ? nsm : MAXCTA;
    if (ncta < 1) ncta = 1;

    size_t smem = (size_t)(NWARPS * DIMV + NWARPS) * sizeof(float); // ~64KB
    cudaFuncSetAttribute(ak_train, cudaFuncAttributeMaxDynamicSharedMemorySize,
                         (int)smem);

    ak_init<<<(DIMV + 255) / 256, 256>>>(theta, out, out_size);
    ak_train<<<ncta, NTHREADS, smem>>>(xn, yn, dxn, dyn, alphas, out, out_size);
}

// round 2
// speedup vs baseline: 1.3822x; 1.3822x over previous
#include <cuda_runtime.h>
#include <cuda_fp16.h>
#include <math.h>

#define DIMV 2048
#define NTR  4096
#define MDEVR 8192
#define TST  500
#define ETA  0.1f
#define NTHREADS 256
#define NWARPS 8
#define MAXCTA 160

// Persistent device state (static allocation — no cudaMalloc anywhere)
__device__ float    g_theta[DIMV];
__device__ float    g_devpart[MAXCTA];
__device__ float    g_gradpart[MAXCTA * DIMV];
__device__ unsigned g_arrive;
// fp16 copies of the big matrices (halves L2 footprint + bytes/step)
__device__ __half   g_xn_h[(size_t)NTR * DIMV];     // 16.8 MB
__device__ __half   g_dxn_h[(size_t)MDEVR * DIMV];  // 33.6 MB

// ---------------------------------------------------------------------------
__global__ void ak_init(const float* __restrict__ theta0,
                        float* __restrict__ out, int out_size) {
    int i = blockIdx.x * blockDim.x + threadIdx.x;
    if (i == 0) g_arrive = 0u;
    if (i < DIMV) g_theta[i] = theta0[i];
    for (int j = TST + 1 + i; j < out_size; j += gridDim.x * blockDim.x)
        out[j] = 0.0f;
}

// fp32 -> fp16 conversion of xn and dev_xn (vectorized, grid-stride)
__global__ void ak_convert(const float* __restrict__ xn,
                           const float* __restrict__ dxn) {
    const size_t n4  = (size_t)NTR * DIMV / 4;
    const size_t m4  = (size_t)MDEVR * DIMV / 4;
    const float4* s0 = (const float4*)xn;
    const float4* s1 = (const float4*)dxn;
    __half2* d0 = (__half2*)g_xn_h;
    __half2* d1 = (__half2*)g_dxn_h;
    size_t stride = (size_t)gridDim.x * blockDim.x;
    for (size_t i = blockIdx.x * (size_t)blockDim.x + threadIdx.x; i < n4; i += stride) {
        float4 v = s0[i];
        d0[2*i+0] = __floats2half2_rn(v.x, v.y);
        d0[2*i+1] = __floats2half2_rn(v.z, v.w);
    }
    for (size_t i = blockIdx.x * (size_t)blockDim.x + threadIdx.x; i < m4; i += stride) {
        float4 v = s1[i];
        d1[2*i+0] = __floats2half2_rn(v.x, v.y);
        d1[2*i+1] = __floats2half2_rn(v.z, v.w);
    }
}

// Grid-wide barrier (atomic counter + generation; gpu-scope fences)
__device__ __forceinline__ void grid_barrier(unsigned nb) {
    __syncthreads();
    if (threadIdx.x == 0) {
        __threadfence();
        unsigned old = atomicAdd(&g_arrive, 1u);
        unsigned target = (old / nb + 1u) * nb;
        while (*((volatile unsigned*)&g_arrive) < target) { }
        __threadfence();
    }
    __syncthreads();
}

__device__ __forceinline__ float warp_sum(float v) {
#pragma unroll
    for (int o = 16; o; o >>= 1) v += __shfl_xor_sync(0xffffffffu, v, o);
    return v;
}

__device__ __forceinline__ float dev_loss_elem(float z, float y) {
    return fmaxf(z, 0.0f) - y * z + log1pf(expf(-fabsf(z)));
}

// accumulate an 8-half chunk (uint4) into a dot product against th[j*8..]
__device__ __forceinline__ void dot8(float& acc, const uint4& u, const float* thj) {
    float2 f;
    f = __half22float2(*(const __half2*)&u.x);
    acc = fmaf(f.x, thj[0], acc); acc = fmaf(f.y, thj[1], acc);
    f = __half22float2(*(const __half2*)&u.y);
    acc = fmaf(f.x, thj[2], acc); acc = fmaf(f.y, thj[3], acc);
    f = __half22float2(*(const __half2*)&u.z);
    acc = fmaf(f.x, thj[4], acc); acc = fmaf(f.y, thj[5], acc);
    f = __half22float2(*(const __half2*)&u.w);
    acc = fmaf(f.x, thj[6], acc); acc = fmaf(f.y, thj[7], acc);
}

__device__ __forceinline__ void grad8(float* gj, const uint4& u, float coef) {
    float2 f;
    f = __half22float2(*(const __half2*)&u.x);
    gj[0] = fmaf(coef, f.x, gj[0]); gj[1] = fmaf(coef, f.y, gj[1]);
    f = __half22float2(*(const __half2*)&u.y);
    gj[2] = fmaf(coef, f.x, gj[2]); gj[3] = fmaf(coef, f.y, gj[3]);
    f = __half22float2(*(const __half2*)&u.z);
    gj[4] = fmaf(coef, f.x, gj[4]); gj[5] = fmaf(coef, f.y, gj[5]);
    f = __half22float2(*(const __half2*)&u.w);
    gj[6] = fmaf(coef, f.x, gj[6]); gj[7] = fmaf(coef, f.y, gj[7]);
}

// ---------------------------------------------------------------------------
__global__ void __launch_bounds__(NTHREADS, 1)
ak_train(const float* __restrict__ yn,  const float* __restrict__ dyn,
         const float* __restrict__ alphas,
         float* __restrict__ out, int out_size) {
    extern __shared__ float sm[];
    float* s_grad = sm;                 // NWARPS * DIMV
    float* s_dev  = sm + NWARPS * DIMV; // NWARPS

    const int tid  = threadIdx.x;
    const int lane = tid & 31;
    const int w    = tid >> 5;
    const int cta  = blockIdx.x;
    const int ncta = gridDim.x;
    const int gw   = cta * NWARPS + w;
    const int nw   = ncta * NWARPS;

    float th[64];   // th[j*8+q] = theta[(j*32+lane)*8 + q]

    for (int t = 0; t < TST; ++t) {
        // ---- theta -> registers
        {
            const float4* t4 = (const float4*)g_theta;
#pragma unroll
            for (int j = 0; j < 8; j++) {
                float4 v0 = t4[(j*32+lane)*2 + 0];
                float4 v1 = t4[(j*32+lane)*2 + 1];
                th[j*8+0]=v0.x; th[j*8+1]=v0.y; th[j*8+2]=v0.z; th[j*8+3]=v0.w;
                th[j*8+4]=v1.x; th[j*8+5]=v1.y; th[j*8+6]=v1.z; th[j*8+7]=v1.w;
            }
        }

        // ---- train rows: dual-row dot + fused gradient accumulation
        float gacc[64];
#pragma unroll
        for (int j = 0; j < 64; j++) gacc[j] = 0.0f;

        int n0 = gw;
        for (; n0 + nw < NTR; n0 += 2*nw) {
            int n1 = n0 + nw;
            const uint4* x0 = (const uint4*)(g_xn_h + (size_t)n0 * DIMV);
            const uint4* x1 = (const uint4*)(g_xn_h + (size_t)n1 * DIMV);
            float a0 = 0.0f, a1 = 0.0f;
#pragma unroll
            for (int j = 0; j < 8; j++) {
                uint4 ua = x0[j*32+lane];
                uint4 ub = x1[j*32+lane];
                dot8(a0, ua, th + j*8);
                dot8(a1, ub, th + j*8);
            }
            float z0 = warp_sum(a0);
            float z1 = warp_sum(a1);
            float s0 = 1.0f / (1.0f + expf(-z0));
            float s1 = 1.0f / (1.0f + expf(-z1));
            float c0 = alphas[(size_t)t * NTR + n0] * (s0 - yn[n0]);
            float c1 = alphas[(size_t)t * NTR + n1] * (s1 - yn[n1]);
#pragma unroll
            for (int j = 0; j < 8; j++) {
                uint4 ua = x0[j*32+lane];   // L1 hits
                uint4 ub = x1[j*32+lane];
                grad8(gacc + j*8, ua, c0);
                grad8(gacc + j*8, ub, c1);
            }
        }
        if (n0 < NTR) {  // tail single row
            const uint4* x0 = (const uint4*)(g_xn_h + (size_t)n0 * DIMV);
            float a0 = 0.0f;
#pragma unroll
            for (int j = 0; j < 8; j++) { uint4 ua = x0[j*32+lane]; dot8(a0, ua, th + j*8); }
            float z0 = warp_sum(a0);
            float s0 = 1.0f / (1.0f + expf(-z0));
            float c0 = alphas[(size_t)t * NTR + n0] * (s0 - yn[n0]);
#pragma unroll
            for (int j = 0; j < 8; j++) { uint4 ua = x0[j*32+lane]; grad8(gacc + j*8, ua, c0); }
        }
        // dump per-warp grad partial (mapping d = (j*32+lane)*8+q)
        {
            float4* gp = (float4*)(s_grad + w * DIMV);
#pragma unroll
            for (int j = 0; j < 8; j++) {
                float4 v;
                v.x=gacc[j*8+0]; v.y=gacc[j*8+1]; v.z=gacc[j*8+2]; v.w=gacc[j*8+3];
                gp[(j*32+lane)*2 + 0] = v;
                v.x=gacc[j*8+4]; v.y=gacc[j*8+5]; v.z=gacc[j*8+6]; v.w=gacc[j*8+7];
                gp[(j*32+lane)*2 + 1] = v;
            }
        }

        // ---- dev loss with current theta (= full_losses[t]), dual-row
        float dsum = 0.0f;
        int m0 = gw;
        for (; m0 + nw < MDEVR; m0 += 2*nw) {
            int m1 = m0 + nw;
            const uint4* x0 = (const uint4*)(g_dxn_h + (size_t)m0 * DIMV);
            const uint4* x1 = (const uint4*)(g_dxn_h + (size_t)m1 * DIMV);
            float a0 = 0.0f, a1 = 0.0f;
#pragma unroll
            for (int j = 0; j < 8; j++) {
                uint4 ua = x0[j*32+lane];
                uint4 ub = x1[j*32+lane];
                dot8(a0, ua, th + j*8);
                dot8(a1, ub, th + j*8);
            }
            float z0 = warp_sum(a0);
            float z1 = warp_sum(a1);
            dsum += dev_loss_elem(z0, dyn[m0]) + dev_loss_elem(z1, dyn[m1]);
        }
        if (m0 < MDEVR) {
            const uint4* x0 = (const uint4*)(g_dxn_h + (size_t)m0 * DIMV);
            float a0 = 0.0f;
#pragma unroll
            for (int j = 0; j < 8; j++) { uint4 ua = x0[j*32+lane]; dot8(a0, ua, th + j*8); }
            float z0 = warp_sum(a0);
            dsum += dev_loss_elem(z0, dyn[m0]);
        }
        if (lane == 0) s_dev[w] = dsum;
        __syncthreads();
        if (tid == 0) {
            float s = 0.0f;
#pragma unroll
            for (int i = 0; i < NWARPS; i++) s += s_dev[i];
            g_devpart[cta] = s;
        }
        // CTA-level grad partial (fixed warp order -> deterministic)
#pragma unroll
        for (int i = 0; i < DIMV / NTHREADS; i++) {
            int d = tid + i * NTHREADS;
            float s = 0.0f;
#pragma unroll
            for (int ww = 0; ww < NWARPS; ww++) s += s_grad[ww * DIMV + d];
            g_gradpart[cta * DIMV + d] = s;
        }

        grid_barrier((unsigned)ncta);

        // ---- phase B: reduce partials, update theta, record loss
        {
            int gid = cta * NTHREADS + tid;
            if (ncta >= 128) {
                int d = gid >> 4, sub = gid & 15;
                if (d < DIMV) {
                    float s = 0.0f;
                    for (int r = sub; r < ncta; r += 16)
                        s += g_gradpart[r * DIMV + d];
#pragma unroll
                    for (int o = 8; o; o >>= 1)
                        s += __shfl_xor_sync(0xffffffffu, s, o);
                    if (sub == 0) g_theta[d] = g_theta[d] - ETA * s;
                }
            } else {
                for (int d = gid; d < DIMV; d += ncta * NTHREADS) {
                    float s = 0.0f;
                    for (int r = 0; r < ncta; r++) s += g_gradpart[r * DIMV + d];
                    g_theta[d] = g_theta[d] - ETA * s;
                }
            }
            if (cta == ncta - 1 && tid == 0) {
                float s = 0.0f;
                for (int c = 0; c < ncta; c++) s += g_devpart[c];
                if (1 + t < out_size) out[1 + t] = s * (1.0f / MDEVR);
            }
        }
        grid_barrier((unsigned)ncta);
    }

    // ---- final dev eval at theta_T; finalize scalar loss
    {
        const float4* t4 = (const float4*)g_theta;
#pragma unroll
        for (int j = 0; j < 8; j++) {
            float4 v0 = t4[(j*32+lane)*2 + 0];
            float4 v1 = t4[(j*32+lane)*2 + 1];
            th[j*8+0]=v0.x; th[j*8+1]=v0.y; th[j*8+2]=v0.z; th[j*8+3]=v0.w;
            th[j*8+4]=v1.x; th[j*8+5]=v1.y; th[j*8+6]=v1.z; th[j*8+7]=v1.w;
        }
        float dsum = 0.0f;
        int m0 = gw;
        for (; m0 + nw < MDEVR; m0 += 2*nw) {
            int m1 = m0 + nw;
            const uint4* x0 = (const uint4*)(g_dxn_h + (size_t)m0 * DIMV);
            const uint4* x1 = (const uint4*)(g_dxn_h + (size_t)m1 * DIMV);
            float a0 = 0.0f, a1 = 0.0f;
#pragma unroll
            for (int j = 0; j < 8; j++) {
                uint4 ua = x0[j*32+lane];
                uint4 ub = x1[j*32+lane];
                dot8(a0, ua, th + j*8);
                dot8(a1, ub, th + j*8);
            }
            dsum += dev_loss_elem(warp_sum(a0), dyn[m0])
                  + dev_loss_elem(warp_sum(a1), dyn[m1]);
        }
        if (m0 < MDEVR) {
            const uint4* x0 = (const uint4*)(g_dxn_h + (size_t)m0 * DIMV);
            float a0 = 0.0f;
#pragma unroll
            for (int j = 0; j < 8; j++) { uint4 ua = x0[j*32+lane]; dot8(a0, ua, th + j*8); }
            dsum += dev_loss_elem(warp_sum(a0), dyn[m0]);
        }
        if (lane == 0) s_dev[w] = dsum;
        __syncthreads();
        if (tid == 0) {
            float s = 0.0f;
#pragma unroll
            for (int i = 0; i < NWARPS; i++) s += s_dev[i];
            g_devpart[cta] = s;
        }
        grid_barrier((unsigned)ncta);
        if (cta == 0 && tid == 0) {
            float s = 0.0f;
            for (int c = 0; c < ncta; c++) s += g_devpart[c];
            float LT = s * (1.0f / MDEVR);
            float isum = 0.0f;
            for (int t = 1; t < TST; t++)
                isum += (1 + t < out_size) ? out[1 + t] : 0.0f;
            isum += LT;
            if (out_size > 0) out[0] = isum / (float)TST;
        }
    }
}

// ---------------------------------------------------------------------------
extern "C" void kernel_launch(void* const* d_in, const int* in_sizes, int n_in,
                              void* d_out, int out_size) {
    const float *theta = nullptr, *alphas = nullptr, *xn = nullptr,
                *yn = nullptr, *dxn = nullptr, *dyn = nullptr;
    for (int i = 0; i < n_in; i++) {
        switch (in_sizes[i]) {
            case DIMV:         theta  = (const float*)d_in[i]; break;
            case TST * NTR:    alphas = (const float*)d_in[i]; break;
            case NTR * DIMV:   xn     = (const float*)d_in[i]; break;
            case NTR:          yn     = (const float*)d_in[i]; break;
            case MDEVR * DIMV: dxn    = (const float*)d_in[i]; break;
            case MDEVR:        dyn    = (const float*)d_in[i]; break;
            default: break;
        }
    }
    float* out = (float*)d_out;

    int dev = 0;
    cudaGetDevice(&dev);
    int nsm = 148;
    cudaDeviceGetAttribute(&nsm, cudaDevAttrMultiProcessorCount, dev);
    int ncta = nsm < MAXCTA ? nsm : MAXCTA;
    if (ncta < 1) ncta = 1;

    size_t smem = (size_t)(NWARPS * DIMV + NWARPS) * sizeof(float); // ~64KB
    cudaFuncSetAttribute(ak_train, cudaFuncAttributeMaxDynamicSharedMemorySize,
                         (int)smem);

    ak_init<<<(DIMV + 255) / 256, 256>>>(theta, out, out_size);
    ak_convert<<<4 * nsm, 256>>>(xn, dxn);
    ak_train<<<ncta, NTHREADS, smem>>>(yn, dyn, alphas, out, out_size);
}